// round 1
// baseline (speedup 1.0000x reference)
#include <cuda_runtime.h>
#include <cuda_bf16.h>

#define BB 8192
#define LL 256
#define NS 9
#define BATCH_PER_WARP 10
#define THREADS 256
#define WARPS_PER_BLOCK (THREADS / 32)
#define BATCH_PER_BLOCK (BATCH_PER_WARP * WARPS_PER_BLOCK)

__global__ __launch_bounds__(THREADS) void crf_fwd_kernel(
    const float* __restrict__ inputs,   // [B, L, 9]
    const int*   __restrict__ path,     // [B, L]
    const float* __restrict__ tran,     // [9, 9]
    const float* __restrict__ initv,    // [9]
    float* __restrict__ out)            // [B]
{
    __shared__ float s_tran[81];
    __shared__ float s_init[9];
    {
        int tid = threadIdx.x;
        if (tid < 81) s_tran[tid] = tran[tid];
        if (tid < 9)  s_init[tid] = initv[tid];
    }
    __syncthreads();

    const int tid  = threadIdx.x;
    const int lane = tid & 31;
    const int gwarp = blockIdx.x * WARPS_PER_BLOCK + (tid >> 5);

    int grp = lane / 3;                 // 0..9 real groups; lanes 30,31 -> grp 10
    int sub = lane - grp * 3;           // 0..2
    const bool active = (grp < BATCH_PER_WARP);
    int base = active ? grp * 3 : 27;   // idle lanes mirror group 9 (harmless)
    if (!active) { grp = 9; sub = lane - 30; if (sub > 2) sub = 2; }

    int b = gwarp * BATCH_PER_WARP + grp;
    const bool valid = active && (b < BB);
    if (b >= BB) b = BB - 1;            // clamp: idle lanes do safe redundant work

    const int j0 = sub * 3;             // this lane owns states j0, j0+1, j0+2

    // E columns for my 3 states: Ec[m][i] = exp(tran[i][j0+m])
    float Ec0[9], Ec1[9], Ec2[9];
    #pragma unroll
    for (int i = 0; i < 9; ++i) {
        Ec0[i] = __expf(s_tran[i * 9 + j0 + 0]);
        Ec1[i] = __expf(s_tran[i * 9 + j0 + 1]);
        Ec2[i] = __expf(s_tran[i * 9 + j0 + 2]);
    }

    const float* xb = inputs + (size_t)b * (LL * NS);
    const int*   pb = path + (size_t)b * LL;

    // t = 0: alpha0 = init + x0  ->  p = exp(init + x0), C = 0
    float x0 = xb[j0 + 0];
    float x1 = xb[j0 + 1];
    float x2 = xb[j0 + 2];
    float p0 = __expf(s_init[j0 + 0] + x0);
    float p1 = __expf(s_init[j0 + 1] + x1);
    float p2 = __expf(s_init[j0 + 2] + x2);

    int pt_prev = pb[0];
    float emit = 0.0f;
    if      (pt_prev == j0 + 0) emit = x0;
    else if (pt_prev == j0 + 1) emit = x1;
    else if (pt_prev == j0 + 2) emit = x2;
    const float initterm = s_init[pt_prev];
    float tracc = 0.0f;
    float C = 0.0f;

    const unsigned FULL = 0xFFFFFFFFu;

    // one scan step (t >= 1)
    auto step = [&](int t) {
        const float* xt = xb + t * NS;
        float xa = xt[j0 + 0];
        float xb_ = xt[j0 + 1];
        float xc = xt[j0 + 2];
        int pt = pb[t];

        // broadcast all 9 p's within the 3-lane group
        float q0 = __shfl_sync(FULL, p0, base + 0);
        float q1 = __shfl_sync(FULL, p1, base + 0);
        float q2 = __shfl_sync(FULL, p2, base + 0);
        float q3 = __shfl_sync(FULL, p0, base + 1);
        float q4 = __shfl_sync(FULL, p1, base + 1);
        float q5 = __shfl_sync(FULL, p2, base + 1);
        float q6 = __shfl_sync(FULL, p0, base + 2);
        float q7 = __shfl_sync(FULL, p1, base + 2);
        float q8 = __shfl_sync(FULL, p2, base + 2);

        float a0 = q0 * Ec0[0];
        float a1 = q0 * Ec1[0];
        float a2 = q0 * Ec2[0];
        a0 = fmaf(q1, Ec0[1], a0); a1 = fmaf(q1, Ec1[1], a1); a2 = fmaf(q1, Ec2[1], a2);
        a0 = fmaf(q2, Ec0[2], a0); a1 = fmaf(q2, Ec1[2], a1); a2 = fmaf(q2, Ec2[2], a2);
        a0 = fmaf(q3, Ec0[3], a0); a1 = fmaf(q3, Ec1[3], a1); a2 = fmaf(q3, Ec2[3], a2);
        a0 = fmaf(q4, Ec0[4], a0); a1 = fmaf(q4, Ec1[4], a1); a2 = fmaf(q4, Ec2[4], a2);
        a0 = fmaf(q5, Ec0[5], a0); a1 = fmaf(q5, Ec1[5], a1); a2 = fmaf(q5, Ec2[5], a2);
        a0 = fmaf(q6, Ec0[6], a0); a1 = fmaf(q6, Ec1[6], a1); a2 = fmaf(q6, Ec2[6], a2);
        a0 = fmaf(q7, Ec0[7], a0); a1 = fmaf(q7, Ec1[7], a1); a2 = fmaf(q7, Ec2[7], a2);
        a0 = fmaf(q8, Ec0[8], a0); a1 = fmaf(q8, Ec1[8], a1); a2 = fmaf(q8, Ec2[8], a2);

        p0 = a0 * __expf(xa);
        p1 = a1 * __expf(xb_);
        p2 = a2 * __expf(xc);

        // path score pieces
        if      (pt == j0 + 0) emit += xa;
        else if (pt == j0 + 1) emit += xb_;
        else if (pt == j0 + 2) emit += xc;
        tracc += s_tran[pt_prev * 9 + pt];
        pt_prev = pt;
    };

    auto renorm = [&]() {
        float loc = p0 + p1 + p2;
        float s = __shfl_sync(FULL, loc, base + 0)
                + __shfl_sync(FULL, loc, base + 1)
                + __shfl_sync(FULL, loc, base + 2);
        C += __logf(s);
        float inv = __fdividef(1.0f, s);
        p0 *= inv; p1 *= inv; p2 *= inv;
    };

    int t = 1;
    #pragma unroll 1
    for (int blk = 0; blk < 31; ++blk) {      // 31 * 8 = 248 steps: t = 1..248
        #pragma unroll
        for (int k = 0; k < 8; ++k) { step(t); ++t; }
        renorm();
    }
    #pragma unroll
    for (int k = 0; k < 7; ++k) { step(t); ++t; }  // t = 249..255

    // final logZ
    float loc = p0 + p1 + p2;
    float s = __shfl_sync(FULL, loc, base + 0)
            + __shfl_sync(FULL, loc, base + 1)
            + __shfl_sync(FULL, loc, base + 2);
    float logZ = C + __logf(s);

    // gather emission partial sums across the 3 lanes
    float esum = __shfl_sync(FULL, emit, base + 0)
               + __shfl_sync(FULL, emit, base + 1)
               + __shfl_sync(FULL, emit, base + 2);

    if (valid && sub == 0) {
        out[b] = logZ - (esum + initterm + tracc);
    }
}

extern "C" void kernel_launch(void* const* d_in, const int* in_sizes, int n_in,
                              void* d_out, int out_size) {
    (void)in_sizes; (void)n_in; (void)out_size;
    const float* inputs = (const float*)d_in[0];
    const int*   path   = (const int*)d_in[1];
    const float* tran   = (const float*)d_in[2];
    const float* initv  = (const float*)d_in[3];
    float* out = (float*)d_out;

    int blocks = (BB + BATCH_PER_BLOCK - 1) / BATCH_PER_BLOCK;  // 103
    crf_fwd_kernel<<<blocks, THREADS>>>(inputs, path, tran, initv, out);
}

// round 2
// speedup vs baseline: 1.7184x; 1.7184x over previous
#include <cuda_runtime.h>
#include <cuda_bf16.h>

#define BB 8192
#define LL 256
#define NS 9
#define BPW 10            // batches per warp (3 lanes each, lanes 30-31 idle)
#define WPB 2             // warps per block
#define THREADS (32*WPB)
#define NWARPS ((BB + BPW - 1) / BPW)          // 820
#define NBLOCKS ((NWARPS + WPB - 1) / WPB)     // 410
#define NCHUNK 32         // 256 timesteps / 8
#define GSTR 73           // smem floats per group slot (73 mod 32 = 9 -> conflict-free)
#define BUFW (GSTR * BPW) // 730 floats per buffer

__global__ __launch_bounds__(THREADS) void crf_fwd_kernel(
    const float* __restrict__ inputs,   // [B, L, 9]
    const int*   __restrict__ path,     // [B, L]
    const float* __restrict__ tran,     // [9, 9]
    const float* __restrict__ initv,    // [9]
    float* __restrict__ out)            // [B]
{
    __shared__ float s_tran[81];
    __shared__ float s_init[9];
    __shared__ float xs[WPB][2][BUFW];

    for (int i = threadIdx.x; i < 81; i += THREADS) s_tran[i] = tran[i];
    if (threadIdx.x < 9) s_init[threadIdx.x] = initv[threadIdx.x];
    __syncthreads();

    const int lane  = threadIdx.x & 31;
    const int w     = threadIdx.x >> 5;
    const int gwarp = blockIdx.x * WPB + w;
    const unsigned FULL = 0xFFFFFFFFu;

    int grp = lane / 3;                  // 0..9 real; lanes 30,31 -> idle
    int sub = lane - grp * 3;
    const bool active = (grp < BPW);
    if (!active) { grp = BPW - 1; sub = lane - 30; if (sub > 2) sub = 2; }
    const int base = grp * 3;
    int b = gwarp * BPW + grp;
    const bool valid = active && (b < BB);
    if (b >= BB) b = BB - 1;             // clamp: redundant safe work
    const int j0 = sub * 3;              // lane owns states j0..j0+2

    // E columns for my 3 states: Ec_m[i] = exp(tran[i][j0+m])
    float Ec0[9], Ec1[9], Ec2[9];
    #pragma unroll
    for (int i = 0; i < 9; ++i) {
        Ec0[i] = __expf(s_tran[i*9 + j0 + 0]);
        Ec1[i] = __expf(s_tran[i*9 + j0 + 1]);
        Ec2[i] = __expf(s_tran[i*9 + j0 + 2]);
    }

    // ---- cooperative-load descriptors: 10 groups x 288B per 8-step chunk ----
    // flat float4 index f = 0..179 ; lane handles f = lane + 32*i, i=0..5
    const float4* gptr[6];
    int  soff[6];
    bool sval[6];
    #pragma unroll
    for (int i = 0; i < 6; ++i) {
        int f = lane + 32 * i;
        bool vv = (f < 180);
        int ff = vv ? f : 0;
        int g = ff / 18, o = ff % 18;    // group, float4-offset within 72-float chunk
        int bf = gwarp * BPW + g;
        if (bf >= BB) bf = BB - 1;
        gptr[i] = (const float4*)inputs + (size_t)bf * (LL * NS / 4) + o;  // row = 576 float4
        soff[i] = g * GSTR + o * 4;
        sval[i] = vv;
    }
    float* mybuf0 = &xs[w][0][0];
    float* mybuf1 = &xs[w][1][0];
    const int off0 = grp * GSTR + sub * 3;

    const int4* pb4 = (const int4*)(path + (size_t)b * LL);

    // ---- stage chunk 0 ----
    float4 v[6];
    #pragma unroll
    for (int i = 0; i < 6; ++i) v[i] = gptr[i][0];
    int4 pA = pb4[0];
    int4 pB = pb4[1];
    #pragma unroll
    for (int i = 0; i < 6; ++i) if (sval[i]) {
        mybuf0[soff[i]+0] = v[i].x; mybuf0[soff[i]+1] = v[i].y;
        mybuf0[soff[i]+2] = v[i].z; mybuf0[soff[i]+3] = v[i].w;
    }
    __syncwarp();

    // ---- t = 0 init ----
    float x0 = mybuf0[off0+0], x1 = mybuf0[off0+1], x2 = mybuf0[off0+2];
    float p0 = __expf(s_init[j0+0] + x0);
    float p1 = __expf(s_init[j0+1] + x1);
    float p2 = __expf(s_init[j0+2] + x2);
    int pt_prev = pA.x;
    float emit = (pt_prev==j0) ? x0 : (pt_prev==j0+1) ? x1 : (pt_prev==j0+2) ? x2 : 0.f;
    const float initterm = s_init[pt_prev];
    float tracc = 0.f;
    float C = 0.f;

    auto step = [&](float xa, float xb_, float xc, int pt) {
        float q0 = __shfl_sync(FULL, p0, base+0);
        float q1 = __shfl_sync(FULL, p1, base+0);
        float q2 = __shfl_sync(FULL, p2, base+0);
        float q3 = __shfl_sync(FULL, p0, base+1);
        float q4 = __shfl_sync(FULL, p1, base+1);
        float q5 = __shfl_sync(FULL, p2, base+1);
        float q6 = __shfl_sync(FULL, p0, base+2);
        float q7 = __shfl_sync(FULL, p1, base+2);
        float q8 = __shfl_sync(FULL, p2, base+2);
        // two parallel chains per output -> shorter critical path
        float a0 = q0*Ec0[0], a1 = q0*Ec1[0], a2 = q0*Ec2[0];
        a0=fmaf(q1,Ec0[1],a0); a1=fmaf(q1,Ec1[1],a1); a2=fmaf(q1,Ec2[1],a2);
        a0=fmaf(q2,Ec0[2],a0); a1=fmaf(q2,Ec1[2],a1); a2=fmaf(q2,Ec2[2],a2);
        a0=fmaf(q3,Ec0[3],a0); a1=fmaf(q3,Ec1[3],a1); a2=fmaf(q3,Ec2[3],a2);
        float h0 = q4*Ec0[4], h1 = q4*Ec1[4], h2 = q4*Ec2[4];
        h0=fmaf(q5,Ec0[5],h0); h1=fmaf(q5,Ec1[5],h1); h2=fmaf(q5,Ec2[5],h2);
        h0=fmaf(q6,Ec0[6],h0); h1=fmaf(q6,Ec1[6],h1); h2=fmaf(q6,Ec2[6],h2);
        h0=fmaf(q7,Ec0[7],h0); h1=fmaf(q7,Ec1[7],h1); h2=fmaf(q7,Ec2[7],h2);
        h0=fmaf(q8,Ec0[8],h0); h1=fmaf(q8,Ec1[8],h1); h2=fmaf(q8,Ec2[8],h2);
        a0 += h0; a1 += h1; a2 += h2;
        p0 = a0 * __expf(xa);
        p1 = a1 * __expf(xb_);
        p2 = a2 * __expf(xc);
        emit += (pt==j0) ? xa : (pt==j0+1) ? xb_ : (pt==j0+2) ? xc : 0.f;
        tracc += s_tran[pt_prev*9 + pt];
        pt_prev = pt;
    };

    auto renorm = [&]() {
        float loc = p0 + p1 + p2;
        float s = __shfl_sync(FULL, loc, base+0)
                + __shfl_sync(FULL, loc, base+1)
                + __shfl_sync(FULL, loc, base+2);
        C += __logf(s);
        float inv = __fdividef(1.f, s);
        p0 *= inv; p1 *= inv; p2 *= inv;
    };

    // ---- prefetch chunk 1, compute chunk 0 (k=1..7) ----
    #pragma unroll
    for (int i = 0; i < 6; ++i) v[i] = gptr[i][18];
    int4 nA = pb4[2], nB = pb4[3];

    #pragma unroll
    for (int k = 1; k < 8; ++k) {
        float xa  = mybuf0[off0 + k*9 + 0];
        float xb_ = mybuf0[off0 + k*9 + 1];
        float xc  = mybuf0[off0 + k*9 + 2];
        int pt = (k==1)?pA.y:(k==2)?pA.z:(k==3)?pA.w:(k==4)?pB.x:(k==5)?pB.y:(k==6)?pB.z:pB.w;
        step(xa, xb_, xc, pt);
    }
    renorm();
    #pragma unroll
    for (int i = 0; i < 6; ++i) if (sval[i]) {
        mybuf1[soff[i]+0] = v[i].x; mybuf1[soff[i]+1] = v[i].y;
        mybuf1[soff[i]+2] = v[i].z; mybuf1[soff[i]+3] = v[i].w;
    }
    __syncwarp();
    pA = nA; pB = nB;

    // ---- main loop: chunks 1..31 ----
    #pragma unroll 1
    for (int c = 1; c < NCHUNK; ++c) {
        float* cbuf = (c & 1) ? mybuf1 : mybuf0;
        float* nbuf = (c & 1) ? mybuf0 : mybuf1;
        if (c + 1 < NCHUNK) {
            #pragma unroll
            for (int i = 0; i < 6; ++i) v[i] = gptr[i][(c+1)*18];
            nA = pb4[(c+1)*2]; nB = pb4[(c+1)*2 + 1];
        }
        #pragma unroll
        for (int k = 0; k < 8; ++k) {
            float xa  = cbuf[off0 + k*9 + 0];
            float xb_ = cbuf[off0 + k*9 + 1];
            float xc  = cbuf[off0 + k*9 + 2];
            int pt = (k==0)?pA.x:(k==1)?pA.y:(k==2)?pA.z:(k==3)?pA.w
                    :(k==4)?pB.x:(k==5)?pB.y:(k==6)?pB.z:pB.w;
            step(xa, xb_, xc, pt);
        }
        if (c + 1 < NCHUNK) {
            renorm();
            #pragma unroll
            for (int i = 0; i < 6; ++i) if (sval[i]) {
                nbuf[soff[i]+0] = v[i].x; nbuf[soff[i]+1] = v[i].y;
                nbuf[soff[i]+2] = v[i].z; nbuf[soff[i]+3] = v[i].w;
            }
            __syncwarp();
            pA = nA; pB = nB;
        }
    }

    // ---- finalize ----
    float loc = p0 + p1 + p2;
    float s = __shfl_sync(FULL, loc, base+0)
            + __shfl_sync(FULL, loc, base+1)
            + __shfl_sync(FULL, loc, base+2);
    float logZ = C + __logf(s);
    float esum = __shfl_sync(FULL, emit, base+0)
               + __shfl_sync(FULL, emit, base+1)
               + __shfl_sync(FULL, emit, base+2);

    if (valid && sub == 0) {
        out[b] = logZ - (esum + initterm + tracc);
    }
}

extern "C" void kernel_launch(void* const* d_in, const int* in_sizes, int n_in,
                              void* d_out, int out_size) {
    (void)in_sizes; (void)n_in; (void)out_size;
    const float* inputs = (const float*)d_in[0];
    const int*   path   = (const int*)d_in[1];
    const float* tran   = (const float*)d_in[2];
    const float* initv  = (const float*)d_in[3];
    float* out = (float*)d_out;

    crf_fwd_kernel<<<NBLOCKS, THREADS>>>(inputs, path, tran, initv, out);
}

// round 3
// speedup vs baseline: 1.7196x; 1.0007x over previous
#include <cuda_runtime.h>
#include <cuda_bf16.h>

#define BB 8192
#define LL 256
#define NS 9
#define BPW 10            // batches per warp (3 lanes each, lanes 30-31 idle)
#define WPB 2
#define THREADS (32*WPB)
#define NWARPS ((BB + BPW - 1) / BPW)          // 820
#define NBLOCKS ((NWARPS + WPB - 1) / WPB)     // 410
#define NCHUNK 32
#define GSTR 73           // floats per group slot (73 mod 32 = 9 -> conflict-free)
#define BUFW (GSTR * BPW)

static __device__ __forceinline__ unsigned long long pk2(float lo, float hi) {
    unsigned long long r; asm("mov.b64 %0, {%1,%2};" : "=l"(r) : "f"(lo), "f"(hi)); return r;
}
static __device__ __forceinline__ void upk2(float& lo, float& hi, unsigned long long v) {
    asm("mov.b64 {%0,%1}, %2;" : "=f"(lo), "=f"(hi) : "l"(v));
}
static __device__ __forceinline__ unsigned long long fma2_(unsigned long long a, unsigned long long b, unsigned long long c) {
    unsigned long long d; asm("fma.rn.f32x2 %0, %1, %2, %3;" : "=l"(d) : "l"(a), "l"(b), "l"(c)); return d;
}
static __device__ __forceinline__ unsigned long long mul2_(unsigned long long a, unsigned long long b) {
    unsigned long long d; asm("mul.rn.f32x2 %0, %1, %2;" : "=l"(d) : "l"(a), "l"(b)); return d;
}
static __device__ __forceinline__ unsigned long long add2_(unsigned long long a, unsigned long long b) {
    unsigned long long d; asm("add.rn.f32x2 %0, %1, %2;" : "=l"(d) : "l"(a), "l"(b)); return d;
}

__global__ __launch_bounds__(THREADS) void crf_fwd_kernel(
    const float* __restrict__ inputs,   // [B, L, 9]
    const int*   __restrict__ path,     // [B, L]
    const float* __restrict__ tran,     // [9, 9]
    const float* __restrict__ initv,    // [9]
    float* __restrict__ out)            // [B]
{
    __shared__ float s_tran[81];
    __shared__ float s_init[9];
    __shared__ float xs[WPB][2][BUFW];

    for (int i = threadIdx.x; i < 81; i += THREADS) s_tran[i] = tran[i];
    if (threadIdx.x < 9) s_init[threadIdx.x] = initv[threadIdx.x];
    __syncthreads();

    const int lane  = threadIdx.x & 31;
    const int w     = threadIdx.x >> 5;
    const int gwarp = blockIdx.x * WPB + w;
    const unsigned FULL = 0xFFFFFFFFu;

    int grp = lane / 3;
    int sub = lane - grp * 3;
    const bool active = (grp < BPW);
    if (!active) { grp = BPW - 1; sub = lane - 30; if (sub > 2) sub = 2; }
    const int base = grp * 3;
    int b = gwarp * BPW + grp;
    const bool valid = active && (b < BB);
    if (b >= BB) b = BB - 1;
    const int j0 = sub * 3;

    // ---- E in registers: packed row-pairs for intermediate, own columns for 2nd step
    unsigned long long Epk[9][4];   // (E[k][0],E[k][1]) .. (E[k][6],E[k][7])
    float Ek8[9];                   // E[k][8]
    unsigned long long Ecolpk[9];   // (E[i][j0], E[i][j0+1])
    float Ecol2[9];                 // E[i][j0+2]
    #pragma unroll
    for (int k = 0; k < 9; ++k) {
        float e0 = __expf(s_tran[k*9+0]), e1 = __expf(s_tran[k*9+1]);
        float e2 = __expf(s_tran[k*9+2]), e3 = __expf(s_tran[k*9+3]);
        float e4 = __expf(s_tran[k*9+4]), e5 = __expf(s_tran[k*9+5]);
        float e6 = __expf(s_tran[k*9+6]), e7 = __expf(s_tran[k*9+7]);
        float e8 = __expf(s_tran[k*9+8]);
        Epk[k][0] = pk2(e0,e1); Epk[k][1] = pk2(e2,e3);
        Epk[k][2] = pk2(e4,e5); Epk[k][3] = pk2(e6,e7);
        Ek8[k] = e8;
        Ecolpk[k] = pk2(__expf(s_tran[k*9+j0]), __expf(s_tran[k*9+j0+1]));
        Ecol2[k]  = __expf(s_tran[k*9+j0+2]);
    }

    // ---- cooperative-load descriptors (R2 scheme) ----
    const float4* gptr[6];
    int  soff[6];
    bool sval[6];
    #pragma unroll
    for (int i = 0; i < 6; ++i) {
        int f = lane + 32 * i;
        bool vv = (f < 180);
        int ff = vv ? f : 0;
        int g = ff / 18, o = ff % 18;
        int bf = gwarp * BPW + g;
        if (bf >= BB) bf = BB - 1;
        gptr[i] = (const float4*)inputs + (size_t)bf * (LL * NS / 4) + o;
        soff[i] = g * GSTR + o * 4;
        sval[i] = vv;
    }
    float* buf0 = &xs[w][0][0];
    float* buf1 = &xs[w][1][0];
    const int goff = grp * GSTR;
    const int off0 = goff + j0;

    const int4* pb4 = (const int4*)(path + (size_t)b * LL);

    // ---- stage chunk 0 ----
    float4 v4[6];
    #pragma unroll
    for (int i = 0; i < 6; ++i) v4[i] = gptr[i][0];
    int4 pA = pb4[0];
    int4 pB = pb4[1];
    #pragma unroll
    for (int i = 0; i < 6; ++i) if (sval[i]) {
        buf0[soff[i]+0] = v4[i].x; buf0[soff[i]+1] = v4[i].y;
        buf0[soff[i]+2] = v4[i].z; buf0[soff[i]+3] = v4[i].w;
    }
    __syncwarp();

    // ---- t = 0 init ----
    float p0 = __expf(s_init[j0+0] + buf0[off0+0]);
    float p1 = __expf(s_init[j0+1] + buf0[off0+1]);
    float p2 = __expf(s_init[j0+2] + buf0[off0+2]);
    int pt_prev = pA.x;
    float emit = buf0[goff + pt_prev];
    const float initterm = s_init[pt_prev];
    float tracc = 0.f;
    float C = 0.f;

    // full intermediate step: from own (p0,p1,p2) via exchange -> v[0..8] = p_{t+1}
    auto interm = [&](const float* obuf, int ko, float* vv) {
        float q0 = __shfl_sync(FULL, p0, base+0);
        float q1 = __shfl_sync(FULL, p1, base+0);
        float q2 = __shfl_sync(FULL, p2, base+0);
        float q3 = __shfl_sync(FULL, p0, base+1);
        float q4 = __shfl_sync(FULL, p1, base+1);
        float q5 = __shfl_sync(FULL, p2, base+1);
        float q6 = __shfl_sync(FULL, p0, base+2);
        float q7 = __shfl_sync(FULL, p1, base+2);
        float q8 = __shfl_sync(FULL, p2, base+2);

        unsigned long long qq, A0, A1, A2, A3, B0, B1, B2, B3;
        float a8, b8;
        qq = pk2(q0,q0);
        A0 = mul2_(qq, Epk[0][0]); A1 = mul2_(qq, Epk[0][1]);
        A2 = mul2_(qq, Epk[0][2]); A3 = mul2_(qq, Epk[0][3]);
        a8 = q0 * Ek8[0];
        qq = pk2(q1,q1);
        A0 = fma2_(qq, Epk[1][0], A0); A1 = fma2_(qq, Epk[1][1], A1);
        A2 = fma2_(qq, Epk[1][2], A2); A3 = fma2_(qq, Epk[1][3], A3);
        a8 = fmaf(q1, Ek8[1], a8);
        qq = pk2(q2,q2);
        A0 = fma2_(qq, Epk[2][0], A0); A1 = fma2_(qq, Epk[2][1], A1);
        A2 = fma2_(qq, Epk[2][2], A2); A3 = fma2_(qq, Epk[2][3], A3);
        a8 = fmaf(q2, Ek8[2], a8);
        qq = pk2(q3,q3);
        A0 = fma2_(qq, Epk[3][0], A0); A1 = fma2_(qq, Epk[3][1], A1);
        A2 = fma2_(qq, Epk[3][2], A2); A3 = fma2_(qq, Epk[3][3], A3);
        a8 = fmaf(q3, Ek8[3], a8);
        qq = pk2(q4,q4);
        B0 = mul2_(qq, Epk[4][0]); B1 = mul2_(qq, Epk[4][1]);
        B2 = mul2_(qq, Epk[4][2]); B3 = mul2_(qq, Epk[4][3]);
        b8 = q4 * Ek8[4];
        qq = pk2(q5,q5);
        B0 = fma2_(qq, Epk[5][0], B0); B1 = fma2_(qq, Epk[5][1], B1);
        B2 = fma2_(qq, Epk[5][2], B2); B3 = fma2_(qq, Epk[5][3], B3);
        b8 = fmaf(q5, Ek8[5], b8);
        qq = pk2(q6,q6);
        B0 = fma2_(qq, Epk[6][0], B0); B1 = fma2_(qq, Epk[6][1], B1);
        B2 = fma2_(qq, Epk[6][2], B2); B3 = fma2_(qq, Epk[6][3], B3);
        b8 = fmaf(q6, Ek8[6], b8);
        qq = pk2(q7,q7);
        B0 = fma2_(qq, Epk[7][0], B0); B1 = fma2_(qq, Epk[7][1], B1);
        B2 = fma2_(qq, Epk[7][2], B2); B3 = fma2_(qq, Epk[7][3], B3);
        b8 = fmaf(q7, Ek8[7], b8);
        qq = pk2(q8,q8);
        B0 = fma2_(qq, Epk[8][0], B0); B1 = fma2_(qq, Epk[8][1], B1);
        B2 = fma2_(qq, Epk[8][2], B2); B3 = fma2_(qq, Epk[8][3], B3);
        b8 = fmaf(q8, Ek8[8], b8);
        A0 = add2_(A0, B0); A1 = add2_(A1, B1);
        A2 = add2_(A2, B2); A3 = add2_(A3, B3);
        a8 += b8;

        float u0,u1,u2,u3,u4,u5,u6,u7;
        upk2(u0,u1,A0); upk2(u2,u3,A1); upk2(u4,u5,A2); upk2(u6,u7,A3);

        float xo0 = obuf[goff + ko*9 + 0];
        float xo1 = obuf[goff + ko*9 + 1];
        float xo2 = obuf[goff + ko*9 + 2];
        float xo3 = obuf[goff + ko*9 + 3];
        float xo4 = obuf[goff + ko*9 + 4];
        float xo5 = obuf[goff + ko*9 + 5];
        float xo6 = obuf[goff + ko*9 + 6];
        float xo7 = obuf[goff + ko*9 + 7];
        float xo8 = obuf[goff + ko*9 + 8];
        vv[0] = u0 * __expf(xo0); vv[1] = u1 * __expf(xo1);
        vv[2] = u2 * __expf(xo2); vv[3] = u3 * __expf(xo3);
        vv[4] = u4 * __expf(xo4); vv[5] = u5 * __expf(xo5);
        vv[6] = u6 * __expf(xo6); vv[7] = u7 * __expf(xo7);
        vv[8] = a8 * __expf(xo8);
    };

    // own-3 second step from full v
    auto ownstep = [&](const float* vv, const float* ebuf, int ke, float inv, bool rn) {
        unsigned long long t0, P0, P1;
        float c2a, c2b;
        t0 = pk2(vv[0], vv[0]); P0 = mul2_(t0, Ecolpk[0]); c2a = vv[0] * Ecol2[0];
        t0 = pk2(vv[1], vv[1]); P0 = fma2_(t0, Ecolpk[1], P0); c2a = fmaf(vv[1], Ecol2[1], c2a);
        t0 = pk2(vv[2], vv[2]); P0 = fma2_(t0, Ecolpk[2], P0); c2a = fmaf(vv[2], Ecol2[2], c2a);
        t0 = pk2(vv[3], vv[3]); P0 = fma2_(t0, Ecolpk[3], P0); c2a = fmaf(vv[3], Ecol2[3], c2a);
        t0 = pk2(vv[4], vv[4]); P1 = mul2_(t0, Ecolpk[4]); c2b = vv[4] * Ecol2[4];
        t0 = pk2(vv[5], vv[5]); P1 = fma2_(t0, Ecolpk[5], P1); c2b = fmaf(vv[5], Ecol2[5], c2b);
        t0 = pk2(vv[6], vv[6]); P1 = fma2_(t0, Ecolpk[6], P1); c2b = fmaf(vv[6], Ecol2[6], c2b);
        t0 = pk2(vv[7], vv[7]); P1 = fma2_(t0, Ecolpk[7], P1); c2b = fmaf(vv[7], Ecol2[7], c2b);
        t0 = pk2(vv[8], vv[8]); P1 = fma2_(t0, Ecolpk[8], P1); c2b = fmaf(vv[8], Ecol2[8], c2b);
        P0 = add2_(P0, P1); c2a += c2b;
        float a0, a1; upk2(a0, a1, P0);
        float xe0 = ebuf[off0 + ke*9 + 0];
        float xe1 = ebuf[off0 + ke*9 + 1];
        float xe2 = ebuf[off0 + ke*9 + 2];
        float e0 = __expf(xe0), e1 = __expf(xe1), e2 = __expf(xe2);
        if (rn) { e0 *= inv; e1 *= inv; e2 *= inv; }
        p0 = a0 * e0; p1 = a1 * e1; p2 = c2a * e2;
    };

    auto do_pair = [&](const float* obuf, int ko, const float* ebuf, int ke,
                       int pto, int pte, bool rn) {
        float vv[9];
        interm(obuf, ko, vv);
        float inv = 1.f;
        if (rn) {
            float s = ((vv[0]+vv[1]) + (vv[2]+vv[3]))
                    + ((vv[4]+vv[5]) + (vv[6]+vv[7])) + vv[8];
            C += __logf(s);
            inv = __fdividef(1.f, s);
        }
        ownstep(vv, ebuf, ke, inv, rn);
        emit  += obuf[goff + ko*9 + pto] + ebuf[goff + ke*9 + pte];
        tracc += s_tran[pt_prev*9 + pto] + s_tran[pto*9 + pte];
        pt_prev = pte;
    };

    // ---- prefetch chunk 1 ----
    #pragma unroll
    for (int i = 0; i < 6; ++i) v4[i] = gptr[i][18];
    int4 nA = pb4[2], nB = pb4[3];

    // ---- main loop: chunks 0..30 (pairs t = 8c+1 .. 8c+8) ----
    #pragma unroll 1
    for (int c = 0; c < NCHUNK - 1; ++c) {
        float* cur = (c & 1) ? buf1 : buf0;
        float* nxt = (c & 1) ? buf0 : buf1;

        do_pair(cur, 1, cur, 2, pA.y, pA.z, false);
        do_pair(cur, 3, cur, 4, pA.w, pB.x, false);
        do_pair(cur, 5, cur, 6, pB.y, pB.z, true);   // renorm every 8 steps

        #pragma unroll
        for (int i = 0; i < 6; ++i) if (sval[i]) {
            nxt[soff[i]+0] = v4[i].x; nxt[soff[i]+1] = v4[i].y;
            nxt[soff[i]+2] = v4[i].z; nxt[soff[i]+3] = v4[i].w;
        }
        __syncwarp();

        do_pair(cur, 7, nxt, 0, pB.w, nA.x, false);  // cross-chunk pair
        pA = nA; pB = nB;

        if (c + 2 < NCHUNK) {
            #pragma unroll
            for (int i = 0; i < 6; ++i) v4[i] = gptr[i][(c+2)*18];
            nA = pb4[(c+2)*2]; nB = pb4[(c+2)*2 + 1];
        }
    }

    // ---- tail: chunk 31 buffer holds t = 248..255; pairs (249,250)(251,252)(253,254), single 255
    {
        float* cur = buf1;  // chunk 31: (31 & 1) == 1
        do_pair(cur, 1, cur, 2, pA.y, pA.z, false);
        do_pair(cur, 3, cur, 4, pA.w, pB.x, false);
        do_pair(cur, 5, cur, 6, pB.y, pB.z, true);

        float vv[9];
        interm(cur, 7, vv);   // t = 255 full
        float s = ((vv[0]+vv[1]) + (vv[2]+vv[3]))
                + ((vv[4]+vv[5]) + (vv[6]+vv[7])) + vv[8];
        float logZ = C + __logf(s);
        emit  += cur[goff + 7*9 + pB.w];
        tracc += s_tran[pt_prev*9 + pB.w];

        if (valid && sub == 0) {
            out[b] = logZ - (emit + initterm + tracc);
        }
    }
}

extern "C" void kernel_launch(void* const* d_in, const int* in_sizes, int n_in,
                              void* d_out, int out_size) {
    (void)in_sizes; (void)n_in; (void)out_size;
    const float* inputs = (const float*)d_in[0];
    const int*   path   = (const int*)d_in[1];
    const float* tran   = (const float*)d_in[2];
    const float* initv  = (const float*)d_in[3];
    float* out = (float*)d_out;

    crf_fwd_kernel<<<NBLOCKS, THREADS>>>(inputs, path, tran, initv, out);
}

// round 5
// speedup vs baseline: 1.7901x; 1.0410x over previous
#include <cuda_runtime.h>
#include <cuda_bf16.h>
#include <cstdint>

#define BB 8192
#define LL 256
#define NS 9
#define GROUPS 64            // 64 groups of 4 timesteps
#define GRAN 11              // float4 granules per batch per group-buffer (9 used + 2 pad)
#define BUF_BYTES (32 * GRAN * 16)   // 5632 B
#define NBUF 4

static __device__ __forceinline__ unsigned long long pk2(float lo, float hi) {
    unsigned long long r; asm("mov.b64 %0, {%1,%2};" : "=l"(r) : "f"(lo), "f"(hi)); return r;
}
static __device__ __forceinline__ void upk2(float& lo, float& hi, unsigned long long v) {
    asm("mov.b64 {%0,%1}, %2;" : "=f"(lo), "=f"(hi) : "l"(v));
}
static __device__ __forceinline__ unsigned long long fma2_(unsigned long long a, unsigned long long b, unsigned long long c) {
    unsigned long long d; asm("fma.rn.f32x2 %0, %1, %2, %3;" : "=l"(d) : "l"(a), "l"(b), "l"(c)); return d;
}
static __device__ __forceinline__ unsigned long long mul2_(unsigned long long a, unsigned long long b) {
    unsigned long long d; asm("mul.rn.f32x2 %0, %1, %2;" : "=l"(d) : "l"(a), "l"(b)); return d;
}
static __device__ __forceinline__ unsigned long long add2_(unsigned long long a, unsigned long long b) {
    unsigned long long d; asm("add.rn.f32x2 %0, %1, %2;" : "=l"(d) : "l"(a), "l"(b)); return d;
}
static __device__ __forceinline__ unsigned int smem_u32(const void* p) {
    unsigned int a; asm("{ .reg .u64 t; cvta.to.shared.u64 t, %1; cvt.u32.u64 %0, t; }" : "=r"(a) : "l"(p)); return a;
}
static __device__ __forceinline__ void cpasync16(unsigned int dst, const void* src) {
    asm volatile("cp.async.ca.shared.global [%0], [%1], 16;" :: "r"(dst), "l"(src));
}
#define CP_COMMIT() asm volatile("cp.async.commit_group;" ::: "memory")
#define CP_WAIT(n)  asm volatile("cp.async.wait_group %0;" :: "n"(n) : "memory")

__global__ __launch_bounds__(32) void crf_fwd_kernel(
    const float* __restrict__ inputs,   // [B, L, 9]
    const int*   __restrict__ path,     // [B, L]
    const float* __restrict__ tran,     // [9, 9]
    const float* __restrict__ initv,    // [9]
    float* __restrict__ out)            // [B]
{
    __shared__ float s_tran[81];
    __shared__ float s_init[9];
    __shared__ __align__(16) float4 xbuf[NBUF][32 * GRAN];

    const int lane = threadIdx.x;
    const int b = blockIdx.x * 32 + lane;

    for (int i = lane; i < 81; i += 32) s_tran[i] = tran[i];
    if (lane < 9) s_init[lane] = initv[lane];
    __syncwarp();

    // E = exp(tran), packed by column pairs: Epk[i][c] = (E[i][2c], E[i][2c+1]), Ek8[i] = E[i][8]
    unsigned long long Epk[9][4];
    float Ek8[9];
    #pragma unroll
    for (int k = 0; k < 9; ++k) {
        float e0 = __expf(s_tran[k*9+0]), e1 = __expf(s_tran[k*9+1]);
        float e2 = __expf(s_tran[k*9+2]), e3 = __expf(s_tran[k*9+3]);
        float e4 = __expf(s_tran[k*9+4]), e5 = __expf(s_tran[k*9+5]);
        float e6 = __expf(s_tran[k*9+6]), e7 = __expf(s_tran[k*9+7]);
        Epk[k][0] = pk2(e0,e1); Epk[k][1] = pk2(e2,e3);
        Epk[k][2] = pk2(e4,e5); Epk[k][3] = pk2(e6,e7);
        Ek8[k] = __expf(s_tran[k*9+8]);
    }

    // cp.async descriptors: flat float4 index f = lane + 32*i covers 32 batches x 9 granules
    const char* gsrc[9];
    unsigned int sdst[9];
    const unsigned int sbase = smem_u32(&xbuf[0][0]);
    #pragma unroll
    for (int i = 0; i < 9; ++i) {
        int f = lane + 32 * i;
        int bi = f / 9, oi = f - bi * 9;
        gsrc[i] = (const char*)inputs + (size_t)(blockIdx.x * 32 + bi) * (LL * NS * 4) + oi * 16;
        sdst[i] = sbase + (unsigned int)(bi * GRAN + oi) * 16;
    }

    auto issue = [&](int g) {
        unsigned int boff = (unsigned int)(g & 3) * BUF_BYTES;
        #pragma unroll
        for (int i = 0; i < 9; ++i)
            cpasync16(sdst[i] + boff, gsrc[i] + g * 144);
        CP_COMMIT();
    };

    issue(0); issue(1); issue(2);

    const unsigned int myrow = sbase + (unsigned int)lane * (GRAN * 16);
    float4 X[9];
    auto loadx = [&](int g) {
        unsigned int a = myrow + (unsigned int)(g & 3) * BUF_BYTES;
        #pragma unroll
        for (int i = 0; i < 9; ++i)
            asm volatile("ld.shared.v4.f32 {%0,%1,%2,%3}, [%4];"
                         : "=f"(X[i].x), "=f"(X[i].y), "=f"(X[i].z), "=f"(X[i].w)
                         : "r"(a + i * 16));
    };

    const float* binp = inputs + (size_t)b * (LL * NS);
    const int4*  pb4  = (const int4*)(path + (size_t)b * LL);

    float p0,p1,p2,p3,p4,p5,p6,p7,p8;
    float C = 0.f, emit = 0.f, tracc = 0.f;
    int ptp;

    // one timestep: alpha' = (E^T p) * exp(x); emission/transition bookkeeping
    auto step = [&](float x0, float x1, float x2, float x3, float x4,
                    float x5, float x6, float x7, float x8, int pt, int t9) {
        float e0 = __expf(x0), e1 = __expf(x1), e2 = __expf(x2);
        float e3 = __expf(x3), e4 = __expf(x4), e5 = __expf(x5);
        float e6 = __expf(x6), e7 = __expf(x7), e8 = __expf(x8);

        unsigned long long q, A0, A1, A2, A3, B0, B1, B2, B3;
        float a8, b8;
        q = pk2(p0,p0);
        A0 = mul2_(q, Epk[0][0]); A1 = mul2_(q, Epk[0][1]);
        A2 = mul2_(q, Epk[0][2]); A3 = mul2_(q, Epk[0][3]);
        a8 = p0 * Ek8[0];
        q = pk2(p1,p1);
        A0 = fma2_(q, Epk[1][0], A0); A1 = fma2_(q, Epk[1][1], A1);
        A2 = fma2_(q, Epk[1][2], A2); A3 = fma2_(q, Epk[1][3], A3);
        a8 = fmaf(p1, Ek8[1], a8);
        q = pk2(p2,p2);
        A0 = fma2_(q, Epk[2][0], A0); A1 = fma2_(q, Epk[2][1], A1);
        A2 = fma2_(q, Epk[2][2], A2); A3 = fma2_(q, Epk[2][3], A3);
        a8 = fmaf(p2, Ek8[2], a8);
        q = pk2(p3,p3);
        A0 = fma2_(q, Epk[3][0], A0); A1 = fma2_(q, Epk[3][1], A1);
        A2 = fma2_(q, Epk[3][2], A2); A3 = fma2_(q, Epk[3][3], A3);
        a8 = fmaf(p3, Ek8[3], a8);
        q = pk2(p4,p4);
        B0 = mul2_(q, Epk[4][0]); B1 = mul2_(q, Epk[4][1]);
        B2 = mul2_(q, Epk[4][2]); B3 = mul2_(q, Epk[4][3]);
        b8 = p4 * Ek8[4];
        q = pk2(p5,p5);
        B0 = fma2_(q, Epk[5][0], B0); B1 = fma2_(q, Epk[5][1], B1);
        B2 = fma2_(q, Epk[5][2], B2); B3 = fma2_(q, Epk[5][3], B3);
        b8 = fmaf(p5, Ek8[5], b8);
        q = pk2(p6,p6);
        B0 = fma2_(q, Epk[6][0], B0); B1 = fma2_(q, Epk[6][1], B1);
        B2 = fma2_(q, Epk[6][2], B2); B3 = fma2_(q, Epk[6][3], B3);
        b8 = fmaf(p6, Ek8[6], b8);
        q = pk2(p7,p7);
        B0 = fma2_(q, Epk[7][0], B0); B1 = fma2_(q, Epk[7][1], B1);
        B2 = fma2_(q, Epk[7][2], B2); B3 = fma2_(q, Epk[7][3], B3);
        b8 = fmaf(p7, Ek8[7], b8);
        q = pk2(p8,p8);
        B0 = fma2_(q, Epk[8][0], B0); B1 = fma2_(q, Epk[8][1], B1);
        B2 = fma2_(q, Epk[8][2], B2); B3 = fma2_(q, Epk[8][3], B3);
        b8 = fmaf(p8, Ek8[8], b8);
        A0 = add2_(A0, B0); A1 = add2_(A1, B1);
        A2 = add2_(A2, B2); A3 = add2_(A3, B3);
        a8 += b8;

        float n0,n1,n2,n3,n4,n5,n6,n7;
        upk2(n0,n1,A0); upk2(n2,n3,A1); upk2(n4,n5,A2); upk2(n6,n7,A3);
        p0 = n0*e0; p1 = n1*e1; p2 = n2*e2; p3 = n3*e3;
        p4 = n4*e4; p5 = n5*e5; p6 = n6*e6; p7 = n7*e7; p8 = a8*e8;

        emit  += __ldg(binp + t9 + pt);
        tracc += s_tran[ptp * 9 + pt];
        ptp = pt;
    };

    auto dogroup = [&](int g, int4 pg) {
        int t9 = g * 36;
        step(X[0].x,X[0].y,X[0].z,X[0].w, X[1].x,X[1].y,X[1].z,X[1].w, X[2].x, pg.x, t9);
        step(X[2].y,X[2].z,X[2].w, X[3].x,X[3].y,X[3].z,X[3].w, X[4].x,X[4].y, pg.y, t9+9);
        step(X[4].z,X[4].w, X[5].x,X[5].y,X[5].z,X[5].w, X[6].x,X[6].y,X[6].z, pg.z, t9+18);
        step(X[6].w, X[7].x,X[7].y,X[7].z,X[7].w, X[8].x,X[8].y,X[8].z,X[8].w, pg.w, t9+27);
    };

    auto renorm = [&]() {
        float s = ((p0+p1)+(p2+p3)) + ((p4+p5)+(p6+p7)) + p8;
        C += __logf(s);
        float inv = __fdividef(1.f, s);
        p0*=inv; p1*=inv; p2*=inv; p3*=inv; p4*=inv;
        p5*=inv; p6*=inv; p7*=inv; p8*=inv;
    };

    // ---- group 0: t=0 init + steps 1..3 ----
    CP_WAIT(2); __syncwarp();
    loadx(0);
    int4 pg = pb4[0];
    p0 = __expf(s_init[0] + X[0].x);
    p1 = __expf(s_init[1] + X[0].y);
    p2 = __expf(s_init[2] + X[0].z);
    p3 = __expf(s_init[3] + X[0].w);
    p4 = __expf(s_init[4] + X[1].x);
    p5 = __expf(s_init[5] + X[1].y);
    p6 = __expf(s_init[6] + X[1].z);
    p7 = __expf(s_init[7] + X[1].w);
    p8 = __expf(s_init[8] + X[2].x);
    ptp = pg.x;
    emit = __ldg(binp + pg.x);
    const float initterm = s_init[pg.x];
    step(X[2].y,X[2].z,X[2].w, X[3].x,X[3].y,X[3].z,X[3].w, X[4].x,X[4].y, pg.y, 9);
    step(X[4].z,X[4].w, X[5].x,X[5].y,X[5].z,X[5].w, X[6].x,X[6].y,X[6].z, pg.z, 18);
    step(X[6].w, X[7].x,X[7].y,X[7].z,X[7].w, X[8].x,X[8].y,X[8].z,X[8].w, pg.w, 27);
    __syncwarp();
    issue(3);

    // ---- main loop: groups 1..60 ----
    #pragma unroll 1
    for (int g = 1; g <= 60; ++g) {
        CP_WAIT(2); __syncwarp();
        loadx(g);
        int4 pgg = pb4[g];
        dogroup(g, pgg);
        __syncwarp();
        issue(g + 3);
        if (g & 1) renorm();     // renorm every 8 steps (after t=7,15,...,239)
    }

    // ---- tail: groups 61..63 (all data already in flight) ----
    CP_WAIT(0); __syncwarp();
    #pragma unroll 1
    for (int g = 61; g <= 63; ++g) {
        loadx(g);
        int4 pgg = pb4[g];
        dogroup(g, pgg);
        if (g == 61) renorm();   // after t=247; final 8 steps un-renormed
    }

    float s = ((p0+p1)+(p2+p3)) + ((p4+p5)+(p6+p7)) + p8;
    float logZ = C + __logf(s);
    out[b] = logZ - (emit + initterm + tracc);
}

extern "C" void kernel_launch(void* const* d_in, const int* in_sizes, int n_in,
                              void* d_out, int out_size) {
    (void)in_sizes; (void)n_in; (void)out_size;
    const float* inputs = (const float*)d_in[0];
    const int*   path   = (const int*)d_in[1];
    const float* tran   = (const float*)d_in[2];
    const float* initv  = (const float*)d_in[3];
    float* out = (float*)d_out;

    crf_fwd_kernel<<<BB / 32, 32>>>(inputs, path, tran, initv, out);
}

// round 6
// speedup vs baseline: 2.5331x; 1.4151x over previous
#include <cuda_runtime.h>
#include <cuda_bf16.h>
#include <cstdint>

#define BB 8192
#define LL 256
#define BPWARP 16                    // batches per warp (2 lanes each)
#define GRAN 11                      // float4 granules per batch row per group (9 data + 2 pad)
#define ROWB (GRAN * 16)             // 176 B
#define BUF_BYTES (BPWARP * ROWB)    // 2816 B
#define NBUF 4

static __device__ __forceinline__ unsigned long long pk2(float lo, float hi) {
    unsigned long long r; asm("mov.b64 %0, {%1,%2};" : "=l"(r) : "f"(lo), "f"(hi)); return r;
}
static __device__ __forceinline__ void upk2(float& lo, float& hi, unsigned long long v) {
    asm("mov.b64 {%0,%1}, %2;" : "=f"(lo), "=f"(hi) : "l"(v));
}
static __device__ __forceinline__ unsigned long long fma2_(unsigned long long a, unsigned long long b, unsigned long long c) {
    unsigned long long d; asm("fma.rn.f32x2 %0, %1, %2, %3;" : "=l"(d) : "l"(a), "l"(b), "l"(c)); return d;
}
static __device__ __forceinline__ unsigned long long mul2_(unsigned long long a, unsigned long long b) {
    unsigned long long d; asm("mul.rn.f32x2 %0, %1, %2;" : "=l"(d) : "l"(a), "l"(b)); return d;
}
static __device__ __forceinline__ unsigned long long add2_(unsigned long long a, unsigned long long b) {
    unsigned long long d; asm("add.rn.f32x2 %0, %1, %2;" : "=l"(d) : "l"(a), "l"(b)); return d;
}
static __device__ __forceinline__ unsigned int smem_u32(const void* p) {
    unsigned int a; asm("{ .reg .u64 t; cvta.to.shared.u64 t, %1; cvt.u32.u64 %0, t; }" : "=r"(a) : "l"(p)); return a;
}
static __device__ __forceinline__ void cpasync16(unsigned int dst, const void* src) {
    asm volatile("cp.async.ca.shared.global [%0], [%1], 16;" :: "r"(dst), "l"(src));
}
static __device__ __forceinline__ float lds_f(unsigned int a) {
    float v; asm volatile("ld.shared.f32 %0, [%1];" : "=f"(v) : "r"(a)); return v;
}
#define CP_COMMIT() asm volatile("cp.async.commit_group;" ::: "memory")
#define CP_WAIT(n)  asm volatile("cp.async.wait_group %0;" :: "n"(n) : "memory")

__global__ __launch_bounds__(32) void crf_fwd_kernel(
    const float* __restrict__ inputs,   // [B, L, 9]
    const int*   __restrict__ path,     // [B, L]
    const float* __restrict__ tran,     // [9, 9]
    const float* __restrict__ initv,    // [9]
    float* __restrict__ out)            // [B]
{
    __shared__ float s_tran[81];
    __shared__ float s_init[10];
    __shared__ __align__(16) char xbuf[NBUF * BUF_BYTES];

    const int lane = threadIdx.x;
    const int pair = lane >> 1;
    const int sub  = lane & 1;
    const int b    = blockIdx.x * BPWARP + pair;
    const unsigned FULL = 0xFFFFFFFFu;

    for (int i = lane; i < 81; i += 32) s_tran[i] = tran[i];
    if (lane < 9) s_init[lane] = initv[lane];
    if (lane == 9) s_init[9] = -1e30f;     // dummy state: exp(-1e30 + x) == 0
    __syncwarp();

    const unsigned int sbase = smem_u32(xbuf);

    // zero pad granules (9,10) of every row in every buffer (never touched by cp.async)
    #pragma unroll
    for (int j = 0; j < 4; ++j) {
        int idx = lane + 32 * j;           // 0..127
        int buf = idx >> 5, rem = idx & 31;
        int row = rem >> 1, gr = 9 + (rem & 1);
        unsigned int a = sbase + (unsigned int)(buf * BUF_BYTES + row * ROWB + gr * 16);
        asm volatile("st.shared.v4.f32 [%0], {%1,%2,%3,%4};"
                     :: "r"(a), "f"(0.f), "f"(0.f), "f"(0.f), "f"(0.f));
    }

    // ---- per-lane E registers ----
    // sources: own m=0..4 (state ownbase+m), remote m=0..4 (state rembase+m)
    // outputs: states ownbase+0..4 (sub1's output 4 = dummy, E col = 0)
    const int ownbase = sub * 5;
    const int rembase = 5 - sub * 5;
    unsigned long long EoA[5], EoB[5], ErA[5], ErB[5];
    float EoS[5], ErS[5];
    #pragma unroll
    for (int m = 0; m < 5; ++m) {
        int so = ownbase + m, sr = rembase + m;
        float eo[5], er[5];
        #pragma unroll
        for (int k = 0; k < 5; ++k) {
            int j = ownbase + k;
            eo[k] = (so < 9 && j < 9) ? __expf(s_tran[so * 9 + j]) : 0.f;
            er[k] = (sr < 9 && j < 9) ? __expf(s_tran[sr * 9 + j]) : 0.f;
        }
        EoA[m] = pk2(eo[0], eo[1]); EoB[m] = pk2(eo[2], eo[3]); EoS[m] = eo[4];
        ErA[m] = pk2(er[0], er[1]); ErB[m] = pk2(er[2], er[3]); ErS[m] = er[4];
    }
    float myini[5];
    #pragma unroll
    for (int k = 0; k < 5; ++k) myini[k] = s_init[ownbase + k];

    // ---- cp.async descriptors: 16 rows x 9 granules = 144 float4 per buffer ----
    const char* gsrc[5];
    unsigned int sdst[5];
    bool cval[5];
    #pragma unroll
    for (int i = 0; i < 5; ++i) {
        int f = lane + 32 * i;
        bool vv = (f < 144);
        int ff = vv ? f : 0;
        int bi = ff / 9, oi = ff - bi * 9;
        gsrc[i] = (const char*)inputs + (size_t)(blockIdx.x * BPWARP + bi) * (LL * 9 * 4) + oi * 16;
        sdst[i] = sbase + (unsigned int)(bi * GRAN + oi) * 16;
        cval[i] = vv;
    }

    auto issue = [&](int g) {
        unsigned int boff = (unsigned int)(g & 3) * BUF_BYTES;
        #pragma unroll
        for (int i = 0; i < 5; ++i)
            if (cval[i]) cpasync16(sdst[i] + boff, gsrc[i] + g * 144);
        CP_COMMIT();
    };

    issue(0); issue(1); issue(2);

    const unsigned int myrowbase = sbase + (unsigned int)pair * ROWB;
    float f[40];
    auto loadx = [&](int g) {
        unsigned int a = myrowbase + (unsigned int)(g & 3) * BUF_BYTES;
        #pragma unroll
        for (int i = 0; i < 10; ++i)
            asm volatile("ld.shared.v4.f32 {%0,%1,%2,%3}, [%4];"
                         : "=f"(f[4*i]), "=f"(f[4*i+1]), "=f"(f[4*i+2]), "=f"(f[4*i+3])
                         : "r"(a + i * 16));
    };

    const int4* pb4 = (const int4*)(path + (size_t)b * LL);

    float p0, p1, p2, p3, p4;
    float C = 0.f, emit = 0.f, tracc = 0.f;
    int ptp;

    // one scan step; x0..x4 are this lane's 5 state scores; rowa = smem row addr of this group
    auto step = [&](float x0, float x1, float x2, float x3, float x4,
                    int pt, unsigned int rowa, int tt) {
        float e0 = __expf(x0), e1 = __expf(x1), e2 = __expf(x2);
        float e3 = __expf(x3), e4 = __expf(x4);

        float r0 = __shfl_xor_sync(FULL, p0, 1);
        float r1 = __shfl_xor_sync(FULL, p1, 1);
        float r2 = __shfl_xor_sync(FULL, p2, 1);
        float r3 = __shfl_xor_sync(FULL, p3, 1);
        float r4 = __shfl_xor_sync(FULL, p4, 1);

        unsigned long long q, A0, A1, B0, B1;
        float a4, b4;
        q = pk2(p0, p0); A0 = mul2_(q, EoA[0]); A1 = mul2_(q, EoB[0]); a4 = p0 * EoS[0];
        q = pk2(p1, p1); A0 = fma2_(q, EoA[1], A0); A1 = fma2_(q, EoB[1], A1); a4 = fmaf(p1, EoS[1], a4);
        q = pk2(p2, p2); A0 = fma2_(q, EoA[2], A0); A1 = fma2_(q, EoB[2], A1); a4 = fmaf(p2, EoS[2], a4);
        q = pk2(p3, p3); A0 = fma2_(q, EoA[3], A0); A1 = fma2_(q, EoB[3], A1); a4 = fmaf(p3, EoS[3], a4);
        q = pk2(p4, p4); A0 = fma2_(q, EoA[4], A0); A1 = fma2_(q, EoB[4], A1); a4 = fmaf(p4, EoS[4], a4);
        q = pk2(r0, r0); B0 = mul2_(q, ErA[0]); B1 = mul2_(q, ErB[0]); b4 = r0 * ErS[0];
        q = pk2(r1, r1); B0 = fma2_(q, ErA[1], B0); B1 = fma2_(q, ErB[1], B1); b4 = fmaf(r1, ErS[1], b4);
        q = pk2(r2, r2); B0 = fma2_(q, ErA[2], B0); B1 = fma2_(q, ErB[2], B1); b4 = fmaf(r2, ErS[2], b4);
        q = pk2(r3, r3); B0 = fma2_(q, ErA[3], B0); B1 = fma2_(q, ErB[3], B1); b4 = fmaf(r3, ErS[3], b4);
        q = pk2(r4, r4); B0 = fma2_(q, ErA[4], B0); B1 = fma2_(q, ErB[4], B1); b4 = fmaf(r4, ErS[4], b4);
        A0 = add2_(A0, B0); A1 = add2_(A1, B1); a4 += b4;

        float n0, n1, n2, n3;
        upk2(n0, n1, A0); upk2(n2, n3, A1);
        p0 = n0 * e0; p1 = n1 * e1; p2 = n2 * e2; p3 = n3 * e3; p4 = a4 * e4;

        // path bookkeeping (redundant-identical in both lanes; broadcast LDS)
        emit  += lds_f(rowa + (unsigned int)((tt * 9 + pt) * 4));
        tracc += s_tran[ptp * 9 + pt];
        ptp = pt;
    };

    auto renorm = [&]() {
        float loc = ((p0 + p1) + (p2 + p3)) + p4;
        float s = loc + __shfl_xor_sync(FULL, loc, 1);
        C += __logf(s);
        float inv = __fdividef(1.f, s);
        p0 *= inv; p1 *= inv; p2 *= inv; p3 *= inv; p4 *= inv;
    };

    // x extraction: lane's 5 values at f[9t + sub*5 + k]  (SELs)
    #define XG(t,k) (sub ? f[9*(t)+5+(k)] : f[9*(t)+(k)])

    // ---- group 0: t=0 init + steps 1..3 ----
    CP_WAIT(2); __syncwarp();
    loadx(0);
    int4 pg = pb4[0];
    unsigned int rowa = myrowbase;   // buffer 0
    p0 = __expf(myini[0] + XG(0,0));
    p1 = __expf(myini[1] + XG(0,1));
    p2 = __expf(myini[2] + XG(0,2));
    p3 = __expf(myini[3] + XG(0,3));
    p4 = __expf(myini[4] + XG(0,4));   // sub1: exp(-1e30+x) = 0
    ptp = pg.x;
    emit = lds_f(rowa + (unsigned int)(pg.x * 4));
    const float initterm = s_init[pg.x];
    step(XG(1,0),XG(1,1),XG(1,2),XG(1,3),XG(1,4), pg.y, rowa, 1);
    step(XG(2,0),XG(2,1),XG(2,2),XG(2,3),XG(2,4), pg.z, rowa, 2);
    step(XG(3,0),XG(3,1),XG(3,2),XG(3,3),XG(3,4), pg.w, rowa, 3);
    __syncwarp();
    issue(3);

    // ---- main loop: groups 1..60 ----
    #pragma unroll 1
    for (int g = 1; g <= 60; ++g) {
        CP_WAIT(2); __syncwarp();
        loadx(g);
        int4 pgg = pb4[g];
        unsigned int ra = myrowbase + (unsigned int)(g & 3) * BUF_BYTES;
        step(XG(0,0),XG(0,1),XG(0,2),XG(0,3),XG(0,4), pgg.x, ra, 0);
        step(XG(1,0),XG(1,1),XG(1,2),XG(1,3),XG(1,4), pgg.y, ra, 1);
        step(XG(2,0),XG(2,1),XG(2,2),XG(2,3),XG(2,4), pgg.z, ra, 2);
        step(XG(3,0),XG(3,1),XG(3,2),XG(3,3),XG(3,4), pgg.w, ra, 3);
        __syncwarp();
        issue(g + 3);
        if (g & 1) renorm();        // every 8 steps
    }

    // ---- tail: groups 61..63 ----
    CP_WAIT(0); __syncwarp();
    #pragma unroll 1
    for (int g = 61; g <= 63; ++g) {
        loadx(g);
        int4 pgg = pb4[g];
        unsigned int ra = myrowbase + (unsigned int)(g & 3) * BUF_BYTES;
        step(XG(0,0),XG(0,1),XG(0,2),XG(0,3),XG(0,4), pgg.x, ra, 0);
        step(XG(1,0),XG(1,1),XG(1,2),XG(1,3),XG(1,4), pgg.y, ra, 1);
        step(XG(2,0),XG(2,1),XG(2,2),XG(2,3),XG(2,4), pgg.z, ra, 2);
        step(XG(3,0),XG(3,1),XG(3,2),XG(3,3),XG(3,4), pgg.w, ra, 3);
        if (g == 61) renorm();
    }
    #undef XG

    float loc = ((p0 + p1) + (p2 + p3)) + p4;
    float s = loc + __shfl_xor_sync(FULL, loc, 1);
    float logZ = C + __logf(s);
    if (sub == 0) {
        out[b] = logZ - (emit + initterm + tracc);
    }
}

extern "C" void kernel_launch(void* const* d_in, const int* in_sizes, int n_in,
                              void* d_out, int out_size) {
    (void)in_sizes; (void)n_in; (void)out_size;
    const float* inputs = (const float*)d_in[0];
    const int*   path   = (const int*)d_in[1];
    const float* tran   = (const float*)d_in[2];
    const float* initv  = (const float*)d_in[3];
    float* out = (float*)d_out;

    crf_fwd_kernel<<<BB / BPWARP, 32>>>(inputs, path, tran, initv, out);
}